// round 16
// baseline (speedup 1.0000x reference)
#include <cuda_runtime.h>
#include <cuda_fp16.h>
#include <stdint.h>
#include <math.h>

#define T_TOK 1024
#define H_DIM 2048
#define I_DIM 1408
#define E_NUM 8

#define NSTG 3
#define STG_B 32768
#define SMEM_TOT (NSTG * STG_B)        // gu: 96 KB -> 2 CTAs/SM
#define DN_STG_B 24576
#define DN_SMEM_TOT (NSTG * DN_STG_B)  // dn: 72 KB -> 2 CTAs/SM

#define EGW_N (E_NUM * I_DIM * H_DIM)
#define SGW_N (I_DIM * H_DIM)
#define X_N   (T_TOK * H_DIM)
#define H_ROWS ((E_NUM + 1) * T_TOK)

#define NPERS 296        // 148 SMs x 2 CTAs
#define GU_NCVT 64       // first 64 gu work items = down-weight conversion
#define GU_NX (I_DIM / 64)   // 22
#define DN_NX (H_DIM / 64)   // 32

// ---------------- device scratch ----------------
__device__ int   g_count[E_NUM];
__device__ int   g_tok[E_NUM * T_TOK];
__device__ float g_wt [E_NUM * T_TOK];
__device__ int   g_ctr_gu, g_ctr_dn;

__device__ __align__(16) __half cx[X_N];
__device__ __align__(16) __half cgw[EGW_N];
__device__ __align__(16) __half cuw[EGW_N];
__device__ __align__(16) __half cdw[EGW_N];
__device__ __align__(16) __half csg[SGW_N], csu[SGW_N], csd[SGW_N];
__device__ __align__(16) __half h_buf[(size_t)H_ROWS * I_DIM];

// ---------------- PTX helpers ----------------
__device__ __forceinline__ uint32_t smem_u32(const void* p) {
    uint32_t a;
    asm("{ .reg .u64 t; cvta.to.shared.u64 t, %1; cvt.u32.u64 %0, t; }" : "=r"(a) : "l"(p));
    return a;
}
__device__ __forceinline__ void cpa(uint32_t dst, const void* src) {
    asm volatile("cp.async.cg.shared.global [%0], [%1], 16;" :: "r"(dst), "l"(src));
}
#define CPA_COMMIT() asm volatile("cp.async.commit_group;" ::: "memory")
#define CPA_WAIT1()  asm volatile("cp.async.wait_group 1;" ::: "memory")

__device__ __forceinline__ void ldmx4(uint32_t* r, uint32_t a) {
    asm volatile("ldmatrix.sync.aligned.m8n8.x4.shared.b16 {%0,%1,%2,%3}, [%4];"
        : "=r"(r[0]), "=r"(r[1]), "=r"(r[2]), "=r"(r[3]) : "r"(a));
}
__device__ __forceinline__ void mma16816(float* c, const uint32_t* a, uint32_t b0, uint32_t b1) {
    asm volatile("mma.sync.aligned.m16n8k16.row.col.f32.f16.f16.f32 "
        "{%0,%1,%2,%3},{%4,%5,%6,%7},{%8,%9},{%0,%1,%2,%3};"
        : "+f"(c[0]), "+f"(c[1]), "+f"(c[2]), "+f"(c[3])
        : "r"(a[0]), "r"(a[1]), "r"(a[2]), "r"(a[3]), "r"(b0), "r"(b1));
}
__device__ __forceinline__ uint32_t h2u(__half2 h) { return *reinterpret_cast<uint32_t*>(&h); }

// 8 fp32 -> 8 fp16 (one uint4 store)
__device__ __forceinline__ void cvt8(const float* __restrict__ src, __half* __restrict__ dst, int i) {
    float4 a = ((const float4*)src)[i * 2];
    float4 b = ((const float4*)src)[i * 2 + 1];
    __half2 h0 = __floats2half2_rn(a.x, a.y);
    __half2 h1 = __floats2half2_rn(a.z, a.w);
    __half2 h2 = __floats2half2_rn(b.x, b.y);
    __half2 h3 = __floats2half2_rn(b.z, b.w);
    ((uint4*)dst)[i] = make_uint4(h2u(h0), h2u(h1), h2u(h2), h2u(h3));
}

// decompose ytile index -> (z, m0). returns z > 8 when out of range.
__device__ __forceinline__ int yt_decompose(int yt, int& m0) {
    int z = 0, rem = yt;
#pragma unroll 1
    for (; z <= E_NUM; z++) {
        int nt = (z < E_NUM) ? ((g_count[z] + 127) >> 7) : (T_TOK / 128);
        if (rem < nt) break;
        rem -= nt;
    }
    m0 = rem * 128;
    return z;
}

// ---------------- small kernels ----------------
__global__ void reset_kernel() {
    int i = threadIdx.x;
    if (i < E_NUM) g_count[i] = 0;
    if (i == 8) g_ctr_gu = 0;
    if (i == 9) g_ctr_dn = 0;
}

// routing (blocks 0..127, warp per token) + zero-out + cvt(x, sg, su, gw, uw)
__global__ void routing_cvt_kernel(const float* __restrict__ x, const float* __restrict__ gw,
                                   const float* __restrict__ egw, const float* __restrict__ euw,
                                   const float* __restrict__ sg, const float* __restrict__ su,
                                   float* __restrict__ out) {
    if (blockIdx.x >= 128) {
        const int NT = (gridDim.x - 128) * 256;
        const int tg = (blockIdx.x - 128) * 256 + threadIdx.x;
        const float4 z4 = make_float4(0.f, 0.f, 0.f, 0.f);
        for (int i = tg; i < (T_TOK * H_DIM) / 4; i += NT) ((float4*)out)[i] = z4;
        for (int i = tg; i < X_N / 8; i += NT) cvt8(x, cx, i);
        for (int i = tg; i < SGW_N / 8; i += NT) { cvt8(sg, csg, i); cvt8(su, csu, i); }
        for (int i = tg; i < EGW_N / 8; i += NT) { cvt8(egw, cgw, i); cvt8(euw, cuw, i); }
        return;
    }
    int warp = (blockIdx.x * blockDim.x + threadIdx.x) >> 5;
    int lane = threadIdx.x & 31;
    if (warp >= T_TOK) return;
    int t = warp;
    float logits[E_NUM];
#pragma unroll
    for (int e = 0; e < E_NUM; e++) logits[e] = 0.0f;
    const float* xr = x + (size_t)t * H_DIM;
    for (int h = lane * 4; h < H_DIM; h += 128) {
        float4 xv = *(const float4*)(xr + h);
#pragma unroll
        for (int e = 0; e < E_NUM; e++) {
            const float* wr = gw + (size_t)e * H_DIM + h;
            logits[e] += xv.x * wr[0] + xv.y * wr[1] + xv.z * wr[2] + xv.w * wr[3];
        }
    }
#pragma unroll
    for (int e = 0; e < E_NUM; e++) {
#pragma unroll
        for (int off = 16; off > 0; off >>= 1)
            logits[e] += __shfl_xor_sync(0xFFFFFFFF, logits[e], off);
    }
    if (lane == 0) {
        int i0 = 0;
#pragma unroll
        for (int e = 1; e < E_NUM; e++) if (logits[e] > logits[i0]) i0 = e;
        int i1 = -1;
#pragma unroll
        for (int e = 0; e < E_NUM; e++) {
            if (e == i0) continue;
            if (i1 < 0 || logits[e] > logits[i1]) i1 = e;
        }
        float e1 = expf(logits[i1] - logits[i0]);
        float inv = 1.0f / (1.0f + e1);
        int s0 = atomicAdd(&g_count[i0], 1);
        g_tok[i0 * T_TOK + s0] = t;  g_wt[i0 * T_TOK + s0] = inv;
        int s1 = atomicAdd(&g_count[i1], 1);
        g_tok[i1 * T_TOK + s1] = t;  g_wt[i1 * T_TOK + s1] = e1 * inv;
    }
}

// ============================================================================
// gate+up GEMM — persistent CTAs with dynamic tile claims.
// Work items: [0, GU_NCVT) = down-weight cvt slices; rest = GEMM tiles
// (yt-major: yt = item / GU_NX, nx = item % GU_NX).
// Tile: BM=128, BN=64 per matrix (gate & up), BK=64, 512 thr = 16 warps
// (4m x 4n), warp tile 32x16 per matrix, pure fp16.
// smem/stage: A 16K | G 8K | U 8K = 32KB. 2 CTAs/SM.
// ============================================================================
__global__ void __launch_bounds__(512, 2) gu_kernel(const float* __restrict__ edw,
                                                    const float* __restrict__ sdw) {
    extern __shared__ __align__(1024) char sm[];
    __shared__ int s_idx;
    const int tid = threadIdx.x, lane = tid & 31, wid = tid >> 5;
    const int wm = wid & 3, wn = wid >> 2;
    const uint32_t sb = smem_u32(sm);
    const int krot = wid & 3;

    // invariant lane constants
    const int lr = tid >> 2, lj = (tid & 3) * 2;
    const uint32_t SA = (uint32_t)(lr & 7) << 4;
    const uint32_t rowA = (uint32_t)(lr * 128);
    uint32_t dA[2];
#pragma unroll
    for (int uu = 0; uu < 2; uu++)
        dA[uu] = rowA + ((((uint32_t)(lj + uu)) << 4) ^ SA);
    const int selB = tid >> 8, rowb = (tid & 255) >> 2, bj = (tid & 3) * 2;
    const uint32_t SB = (uint32_t)(rowb & 7) << 4;
    const uint32_t rowBoff = 16384u + (uint32_t)selB * 8192u + (uint32_t)(rowb * 128);
    const int ra = wm * 32 + (((lane >> 3) & 1) << 3) + (lane & 7);
    const uint32_t Sa = (uint32_t)(ra & 7) << 4;
    const int rbn = wn * 16 + (((lane >> 3) & 1) << 3) + (lane & 7);
    const uint32_t Sbn = (uint32_t)(rbn & 7) << 4;
    const uint32_t g2 = (uint32_t)(lane >> 4) << 4;

    for (;;) {
        if (tid == 0) s_idx = atomicAdd(&g_ctr_gu, 1);
        __syncthreads();
        const int idx = s_idx;

        if (idx < GU_NCVT) {   // hidden down-weight conversion
            const int NT = GU_NCVT * 512;
            int tg = idx * 512 + tid;
            for (int i = tg; i < EGW_N / 8; i += NT) cvt8(edw, cdw, i);
            for (int i = tg; i < SGW_N / 8; i += NT) cvt8(sdw, csd, i);
            continue;
        }
        const int t2 = idx - GU_NCVT;
        const int nx = t2 % GU_NX, yt = t2 / GU_NX;
        int m0;
        const int z = yt_decompose(yt, m0);
        if (z > E_NUM) break;
        const int count = (z < E_NUM) ? g_count[z] : T_TOK;
        const int n0 = nx * 64;

        // ---- per-tile loader pointers ----
        const int mrow = m0 + lr;
        int tok = (z < E_NUM) ? ((mrow < count) ? g_tok[z * T_TOK + mrow] : 0) : mrow;
        const char* srcA = (const char*)(cx + (size_t)tok * H_DIM);
        const __half* wbh;
        if (z < E_NUM) {
            size_t eo = (size_t)z * I_DIM * H_DIM;
            wbh = selB ? cuw + eo : cgw + eo;
        } else {
            wbh = selB ? csu : csg;
        }
        const char* srcB = (const char*)(wbh + (size_t)(n0 + rowb) * H_DIM);

        auto load_stage = [&](int chunk, int stg) {
            uint32_t base = sb + stg * STG_B;
            int koff = chunk * 128;
#pragma unroll
            for (int uu = 0; uu < 2; uu++)
                cpa(base + dA[uu], srcA + koff + (lj + uu) * 16);
#pragma unroll
            for (int uu = 0; uu < 2; uu++) {
                uint32_t u = (uint32_t)(bj + uu);
                cpa(base + rowBoff + ((u << 4) ^ SB), srcB + koff + u * 16);
            }
        };

        float acc[2][2][2][4];
#pragma unroll
        for (int a = 0; a < 2; a++)
#pragma unroll
            for (int b = 0; b < 2; b++)
#pragma unroll
                for (int c = 0; c < 2; c++)
#pragma unroll
                    for (int d = 0; d < 4; d++) acc[a][b][c][d] = 0.0f;

        load_stage(0, 0); CPA_COMMIT();
        load_stage(1, 1); CPA_COMMIT();

        const int NC = H_DIM / 64;  // 32
        for (int c = 0; c < NC; c++) {
            CPA_WAIT1();
            __syncthreads();
            if (c + 2 < NC) load_stage(c + 2, (c + 2) % NSTG);
            CPA_COMMIT();
            uint32_t base = sb + (c % NSTG) * STG_B;
#pragma unroll
            for (int ks0 = 0; ks0 < 4; ks0++) {
                const int ks = (ks0 + krot) & 3;
                uint32_t kx = ((uint32_t)ks << 5) | g2;
                uint32_t Ah[2][4];
#pragma unroll
                for (int mf = 0; mf < 2; mf++) {
                    uint32_t ro = (uint32_t)((ra + mf * 16) * 128);
                    ldmx4(Ah[mf], base + ro + (kx ^ Sa));
                }
#pragma unroll
                for (int mat = 0; mat < 2; mat++) {
                    uint32_t bh[4];
                    uint32_t bo = base + 16384u + (uint32_t)mat * 8192u + (uint32_t)(rbn * 128);
                    ldmx4(bh, bo + (kx ^ Sbn));
#pragma unroll
                    for (int mf = 0; mf < 2; mf++) {
#pragma unroll
                        for (int nf = 0; nf < 2; nf++)
                            mma16816(acc[mat][mf][nf], Ah[mf], bh[nf], bh[nf + 2]);
                    }
                }
            }
        }

        // ---- epilogue: silu(g)*u -> h (fp16) ----
        const size_t rowbase = (z < E_NUM) ? (size_t)z * T_TOK : (size_t)E_NUM * T_TOK;
#pragma unroll
        for (int mf = 0; mf < 2; mf++) {
            int R0 = m0 + wm * 32 + mf * 16 + (lane >> 2);
#pragma unroll
            for (int nf = 0; nf < 2; nf++) {
                int C = n0 + wn * 16 + nf * 8 + (lane & 3) * 2;
                float* gf = acc[0][mf][nf];
                float* uf = acc[1][mf][nf];
#pragma unroll
                for (int hr = 0; hr < 2; hr++) {
                    int R = R0 + hr * 8;
                    if (R < count) {
                        float ga = gf[hr * 2], gb = gf[hr * 2 + 1];
                        float ua = uf[hr * 2], ub = uf[hr * 2 + 1];
                        float ha = ga / (1.0f + __expf(-ga)) * ua;
                        float hb = gb / (1.0f + __expf(-gb)) * ub;
                        *(__half2*)(h_buf + (rowbase + R) * (size_t)I_DIM + C) =
                            __floats2half2_rn(ha, hb);
                    }
                }
            }
        }
    }
}

// ============================================================================
// down GEMM — persistent CTAs with dynamic tile claims.
// Tile: BM=128, BN=64, BK=64, 512 thr = 16 warps (4m x 4n), warp 32x16.
// smem/stage: A 16K | B 8K = 24KB. 2 CTAs/SM.
// ============================================================================
__global__ void __launch_bounds__(512, 2) dn_kernel(float* __restrict__ out) {
    extern __shared__ __align__(1024) char sm[];
    __shared__ int s_idx;
    const int tid = threadIdx.x, lane = tid & 31, wid = tid >> 5;
    const int wm = wid & 3, wn = wid >> 2;
    const uint32_t sb = smem_u32(sm);
    const int krot = wid & 3;

    const int lr = tid >> 2, lj = (tid & 3) * 2;
    const uint32_t SA = (uint32_t)(lr & 7) << 4;
    const uint32_t rowA = (uint32_t)(lr * 128);
    uint32_t dA[2];
#pragma unroll
    for (int uu = 0; uu < 2; uu++)
        dA[uu] = rowA + ((((uint32_t)(lj + uu)) << 4) ^ SA);
    const int rowb = tid >> 3, bu = tid & 7;
    const uint32_t SB = (uint32_t)(rowb & 7) << 4;
    const uint32_t dB = 16384u + (uint32_t)(rowb * 128) + ((((uint32_t)bu) << 4) ^ SB);
    const int ra = wm * 32 + (((lane >> 3) & 1) << 3) + (lane & 7);
    const uint32_t Sa = (uint32_t)(ra & 7) << 4;
    const int rbn = wn * 16 + (((lane >> 3) & 1) << 3) + (lane & 7);
    const uint32_t Sbn = (uint32_t)(rbn & 7) << 4;
    const uint32_t g2 = (uint32_t)(lane >> 4) << 4;

    for (;;) {
        if (tid == 0) s_idx = atomicAdd(&g_ctr_dn, 1);
        __syncthreads();
        const int idx = s_idx;
        const int nx = idx % DN_NX, yt = idx / DN_NX;
        int m0;
        const int z = yt_decompose(yt, m0);
        if (z > E_NUM) break;
        const int count = (z < E_NUM) ? g_count[z] : T_TOK;
        const int n0 = nx * 64;
        const size_t rowbase = (z < E_NUM) ? (size_t)z * T_TOK : (size_t)E_NUM * T_TOK;

        const char* srcA = (const char*)(h_buf + (rowbase + m0 + lr) * (size_t)I_DIM);
        const __half* wdh = (z < E_NUM) ? cdw + (size_t)z * H_DIM * I_DIM : csd;
        const char* srcB = (const char*)(wdh + (size_t)(n0 + rowb) * I_DIM);

        auto load_stage = [&](int chunk, int stg) {
            uint32_t base = sb + stg * DN_STG_B;
            int koff = chunk * 128;
#pragma unroll
            for (int uu = 0; uu < 2; uu++)
                cpa(base + dA[uu], srcA + koff + (lj + uu) * 16);
            cpa(base + dB, srcB + koff + bu * 16);
        };

        float acc[2][2][4];
#pragma unroll
        for (int a = 0; a < 2; a++)
#pragma unroll
            for (int b = 0; b < 2; b++)
#pragma unroll
                for (int c = 0; c < 4; c++) acc[a][b][c] = 0.0f;

        load_stage(0, 0); CPA_COMMIT();
        load_stage(1, 1); CPA_COMMIT();

        const int NC = I_DIM / 64;  // 22
        for (int c = 0; c < NC; c++) {
            CPA_WAIT1();
            __syncthreads();
            if (c + 2 < NC) load_stage(c + 2, (c + 2) % NSTG);
            CPA_COMMIT();
            uint32_t base = sb + (c % NSTG) * DN_STG_B;
#pragma unroll
            for (int ks0 = 0; ks0 < 4; ks0++) {
                const int ks = (ks0 + krot) & 3;
                uint32_t kx = ((uint32_t)ks << 5) | g2;
                uint32_t Ah[2][4];
#pragma unroll
                for (int mf = 0; mf < 2; mf++) {
                    uint32_t ro = (uint32_t)((ra + mf * 16) * 128);
                    ldmx4(Ah[mf], base + ro + (kx ^ Sa));
                }
                uint32_t bh[4];
                ldmx4(bh, base + 16384u + (uint32_t)(rbn * 128) + (kx ^ Sbn));
#pragma unroll
                for (int mf = 0; mf < 2; mf++) {
#pragma unroll
                    for (int nf = 0; nf < 2; nf++)
                        mma16816(acc[mf][nf], Ah[mf], bh[nf], bh[nf + 2]);
                }
            }
        }

        // ---- epilogue: weighted atomic scatter ----
#pragma unroll
        for (int mf = 0; mf < 2; mf++) {
            int R0 = m0 + wm * 32 + mf * 16 + (lane >> 2);
#pragma unroll
            for (int hr = 0; hr < 2; hr++) {
                int R = R0 + hr * 8;
                if (R < count) {
                    int t; float wt;
                    if (z < E_NUM) { t = g_tok[z * T_TOK + R]; wt = g_wt[z * T_TOK + R]; }
                    else           { t = R; wt = 1.0f; }
                    float* orow = out + (size_t)t * H_DIM;
#pragma unroll
                    for (int nf = 0; nf < 2; nf++) {
                        int C = n0 + wn * 16 + nf * 8 + (lane & 3) * 2;
                        atomicAdd(&orow[C],     wt * acc[mf][nf][hr * 2]);
                        atomicAdd(&orow[C + 1], wt * acc[mf][nf][hr * 2 + 1]);
                    }
                }
            }
        }
    }
}

// ---------------- launch ----------------
extern "C" void kernel_launch(void* const* d_in, const int* in_sizes, int n_in,
                              void* d_out, int out_size) {
    const float* x   = (const float*)d_in[0];
    const float* gw  = (const float*)d_in[1];
    const float* egw = (const float*)d_in[2];
    const float* euw = (const float*)d_in[3];
    const float* edw = (const float*)d_in[4];
    const float* sgw = (const float*)d_in[5];
    const float* suw = (const float*)d_in[6];
    const float* sdw = (const float*)d_in[7];
    float* out = (float*)d_out;

    cudaFuncSetAttribute(gu_kernel, cudaFuncAttributeMaxDynamicSharedMemorySize, SMEM_TOT);
    cudaFuncSetAttribute(dn_kernel, cudaFuncAttributeMaxDynamicSharedMemorySize, DN_SMEM_TOT);

    // 1: reset routing counts + work-queue counters
    reset_kernel<<<1, 32>>>();
    // 2: routing (blocks 0..127) + zero-out + all pre-GEMM conversions
    routing_cvt_kernel<<<128 + 2960, 256>>>(x, gw, egw, euw, sgw, suw, out);
    // 3: gate+up GEMM, persistent (includes hidden down-weight conversion)
    gu_kernel<<<NPERS, 512, SMEM_TOT>>>(edw, sdw);
    // 4: down GEMM, persistent
    dn_kernel<<<NPERS, 512, DN_SMEM_TOT>>>(out);
}

// round 17
// speedup vs baseline: 1.0700x; 1.0700x over previous
#include <cuda_runtime.h>
#include <cuda_fp16.h>
#include <stdint.h>
#include <math.h>

#define T_TOK 1024
#define H_DIM 2048
#define I_DIM 1408
#define E_NUM 8

#define NSTG 3
#define STG_B 32768
#define SMEM_TOT (NSTG * STG_B)        // gu: 96 KB -> 2 CTAs/SM
#define DN_STG_B 32768
#define DN_SMEM_TOT (NSTG * DN_STG_B)  // dn: 96 KB -> 2 CTAs/SM

#define EGW_N (E_NUM * I_DIM * H_DIM)
#define SGW_N (I_DIM * H_DIM)
#define X_N   (T_TOK * H_DIM)
#define H_ROWS ((E_NUM + 1) * T_TOK)

// ---------------- device scratch ----------------
__device__ int   g_count[E_NUM];
__device__ int   g_tok[E_NUM * T_TOK];
__device__ float g_wt [E_NUM * T_TOK];

__device__ __align__(16) __half cx[X_N];
__device__ __align__(16) __half cgw[EGW_N];
__device__ __align__(16) __half cuw[EGW_N];
__device__ __align__(16) __half cdw[EGW_N];
__device__ __align__(16) __half csg[SGW_N], csu[SGW_N], csd[SGW_N];
__device__ __align__(16) __half h_buf[(size_t)H_ROWS * I_DIM];

// ---------------- PTX helpers ----------------
__device__ __forceinline__ uint32_t smem_u32(const void* p) {
    uint32_t a;
    asm("{ .reg .u64 t; cvta.to.shared.u64 t, %1; cvt.u32.u64 %0, t; }" : "=r"(a) : "l"(p));
    return a;
}
__device__ __forceinline__ void cpa(uint32_t dst, const void* src) {
    asm volatile("cp.async.cg.shared.global [%0], [%1], 16;" :: "r"(dst), "l"(src));
}
#define CPA_COMMIT() asm volatile("cp.async.commit_group;" ::: "memory")
#define CPA_WAIT1()  asm volatile("cp.async.wait_group 1;" ::: "memory")

__device__ __forceinline__ void ldmx4(uint32_t* r, uint32_t a) {
    asm volatile("ldmatrix.sync.aligned.m8n8.x4.shared.b16 {%0,%1,%2,%3}, [%4];"
        : "=r"(r[0]), "=r"(r[1]), "=r"(r[2]), "=r"(r[3]) : "r"(a));
}
__device__ __forceinline__ void mma16816(float* c, const uint32_t* a, uint32_t b0, uint32_t b1) {
    asm volatile("mma.sync.aligned.m16n8k16.row.col.f32.f16.f16.f32 "
        "{%0,%1,%2,%3},{%4,%5,%6,%7},{%8,%9},{%0,%1,%2,%3};"
        : "+f"(c[0]), "+f"(c[1]), "+f"(c[2]), "+f"(c[3])
        : "r"(a[0]), "r"(a[1]), "r"(a[2]), "r"(a[3]), "r"(b0), "r"(b1));
}
__device__ __forceinline__ uint32_t h2u(__half2 h) { return *reinterpret_cast<uint32_t*>(&h); }

// 8 fp32 -> 8 fp16 (one uint4 store)
__device__ __forceinline__ void cvt8(const float* __restrict__ src, __half* __restrict__ dst, int i) {
    float4 a = ((const float4*)src)[i * 2];
    float4 b = ((const float4*)src)[i * 2 + 1];
    __half2 h0 = __floats2half2_rn(a.x, a.y);
    __half2 h1 = __floats2half2_rn(a.z, a.w);
    __half2 h2 = __floats2half2_rn(b.x, b.y);
    __half2 h3 = __floats2half2_rn(b.z, b.w);
    ((uint4*)dst)[i] = make_uint4(h2u(h0), h2u(h1), h2u(h2), h2u(h3));
}

// ---------------- small kernels ----------------
// grid-stride segmented: zero out + reset counts + cvt(x, shared gate, shared up)
__global__ void zero_cvt_kernel(float* __restrict__ out, const float* __restrict__ x,
                                const float* __restrict__ sg, const float* __restrict__ su) {
    const int tid = blockIdx.x * blockDim.x + threadIdx.x;
    const int NT = gridDim.x * blockDim.x;
    if (tid < E_NUM) g_count[tid] = 0;
    const float4 z4 = make_float4(0.f, 0.f, 0.f, 0.f);
    for (int i = tid; i < (T_TOK * H_DIM) / 4; i += NT) ((float4*)out)[i] = z4;
    for (int i = tid; i < X_N / 8; i += NT) cvt8(x, cx, i);
    for (int i = tid; i < SGW_N / 8; i += NT) { cvt8(sg, csg, i); cvt8(su, csu, i); }
}

// routing (blocks 0..127, warp per token) + gw/uw conversion (remaining blocks)
__global__ void routing_cvt_kernel(const float* __restrict__ x, const float* __restrict__ gw,
                                   const float* __restrict__ egw, const float* __restrict__ euw) {
    if (blockIdx.x >= 128) {
        const int NT = (gridDim.x - 128) * 256;
        const int tg = (blockIdx.x - 128) * 256 + threadIdx.x;
        for (int i = tg; i < EGW_N / 8; i += NT) { cvt8(egw, cgw, i); cvt8(euw, cuw, i); }
        return;
    }
    int warp = (blockIdx.x * blockDim.x + threadIdx.x) >> 5;
    int lane = threadIdx.x & 31;
    if (warp >= T_TOK) return;
    int t = warp;
    float logits[E_NUM];
#pragma unroll
    for (int e = 0; e < E_NUM; e++) logits[e] = 0.0f;
    const float* xr = x + (size_t)t * H_DIM;
    for (int h = lane * 4; h < H_DIM; h += 128) {
        float4 xv = *(const float4*)(xr + h);
#pragma unroll
        for (int e = 0; e < E_NUM; e++) {
            const float* wr = gw + (size_t)e * H_DIM + h;
            logits[e] += xv.x * wr[0] + xv.y * wr[1] + xv.z * wr[2] + xv.w * wr[3];
        }
    }
#pragma unroll
    for (int e = 0; e < E_NUM; e++) {
#pragma unroll
        for (int off = 16; off > 0; off >>= 1)
            logits[e] += __shfl_xor_sync(0xFFFFFFFF, logits[e], off);
    }
    if (lane == 0) {
        int i0 = 0;
#pragma unroll
        for (int e = 1; e < E_NUM; e++) if (logits[e] > logits[i0]) i0 = e;
        int i1 = -1;
#pragma unroll
        for (int e = 0; e < E_NUM; e++) {
            if (e == i0) continue;
            if (i1 < 0 || logits[e] > logits[i1]) i1 = e;
        }
        float e1 = expf(logits[i1] - logits[i0]);
        float inv = 1.0f / (1.0f + e1);
        int s0 = atomicAdd(&g_count[i0], 1);
        g_tok[i0 * T_TOK + s0] = t;  g_wt[i0 * T_TOK + s0] = inv;
        int s1 = atomicAdd(&g_count[i1], 1);
        g_tok[i1 * T_TOK + s1] = t;  g_wt[i1 * T_TOK + s1] = e1 * inv;
    }
}

// ============================================================================
// gate+up GEMM: BM=128, BN=64 per matrix (gate & up), BK=64, 512 thr = 16 warps
// (4m x 4n), warp tile 32x16 per matrix, pure fp16.  z = 0..7 routed, 8 shared,
// z = 9: grid-stride conversion of down weights (edw, sdw) hidden under gu.
// ks order rotated per warp to de-phase LDSM bursts after each barrier.
// smem/stage: A 16K | G 8K | U 8K = 32KB. 2 CTAs/SM.
// ============================================================================
__global__ void __launch_bounds__(512, 2) gu_kernel(const float* __restrict__ edw,
                                                    const float* __restrict__ sdw) {
    extern __shared__ __align__(1024) char sm[];
    const int z = blockIdx.z;
    if (z == 9) {
        const int NT = 22 * 8 * 512;
        int tg = (blockIdx.y * 22 + blockIdx.x) * 512 + threadIdx.x;
        for (int i = tg; i < EGW_N / 8; i += NT) cvt8(edw, cdw, i);
        for (int i = tg; i < SGW_N / 8; i += NT) cvt8(sdw, csd, i);
        return;
    }
    const int count = (z < E_NUM) ? g_count[z] : T_TOK;
    const int m0 = blockIdx.y * 128;
    if (m0 >= count) return;
    const int n0 = blockIdx.x * 64;

    const int tid = threadIdx.x, lane = tid & 31, wid = tid >> 5;
    const int wm = wid & 3, wn = wid >> 2;
    const uint32_t sb = smem_u32(sm);

    // ---- loader: A — 128 rows, 4 thr/row, 2 units each ----
    const int lr = tid >> 2, lj = (tid & 3) * 2;
    const int mrow = m0 + lr;
    int tok = (z < E_NUM) ? ((mrow < count) ? g_tok[z * T_TOK + mrow] : 0) : mrow;
    const char* srcA = (const char*)(cx + (size_t)tok * H_DIM);
    const uint32_t SA = (uint32_t)(lr & 7) << 4;
    const uint32_t rowA = (uint32_t)(lr * 128);
    uint32_t dA[2];
#pragma unroll
    for (int uu = 0; uu < 2; uu++)
        dA[uu] = rowA + ((((uint32_t)(lj + uu)) << 4) ^ SA);

    // ---- loader: B — 2 buffers (G, U), 64 rows, 4 thr/row, 2 units ----
    const int selB = tid >> 8, rowb = (tid & 255) >> 2, bj = (tid & 3) * 2;
    const __half* wbh;
    if (z < E_NUM) {
        size_t eo = (size_t)z * I_DIM * H_DIM;
        wbh = selB ? cuw + eo : cgw + eo;
    } else {
        wbh = selB ? csu : csg;
    }
    const char* srcB = (const char*)(wbh + (size_t)(n0 + rowb) * H_DIM);
    const uint32_t SB = (uint32_t)(rowb & 7) << 4;
    const uint32_t rowBoff = 16384u + (uint32_t)selB * 8192u + (uint32_t)(rowb * 128);

    auto load_stage = [&](int chunk, int stg) {
        uint32_t base = sb + stg * STG_B;
        int koff = chunk * 128;   // 64 fp16 * 2B
#pragma unroll
        for (int uu = 0; uu < 2; uu++)
            cpa(base + dA[uu], srcA + koff + (lj + uu) * 16);
#pragma unroll
        for (int uu = 0; uu < 2; uu++) {
            uint32_t u = (uint32_t)(bj + uu);
            cpa(base + rowBoff + ((u << 4) ^ SB), srcB + koff + u * 16);
        }
    };

    const int ra = wm * 32 + (((lane >> 3) & 1) << 3) + (lane & 7);
    const uint32_t Sa = (uint32_t)(ra & 7) << 4;
    const int rbn = wn * 16 + (((lane >> 3) & 1) << 3) + (lane & 7);
    const uint32_t Sbn = (uint32_t)(rbn & 7) << 4;
    const uint32_t g2 = (uint32_t)(lane >> 4) << 4;
    const int krot = wid & 3;   // per-warp ks phase rotation

    float acc[2][2][2][4];   // [mat][mf][nf][4]
#pragma unroll
    for (int a = 0; a < 2; a++)
#pragma unroll
        for (int b = 0; b < 2; b++)
#pragma unroll
            for (int c = 0; c < 2; c++)
#pragma unroll
                for (int d = 0; d < 4; d++) acc[a][b][c][d] = 0.0f;

    load_stage(0, 0); CPA_COMMIT();
    load_stage(1, 1); CPA_COMMIT();

    const int NC = H_DIM / 64;  // 32
    for (int c = 0; c < NC; c++) {
        CPA_WAIT1();
        __syncthreads();
        if (c + 2 < NC) load_stage(c + 2, (c + 2) % NSTG);
        CPA_COMMIT();
        uint32_t base = sb + (c % NSTG) * STG_B;
#pragma unroll
        for (int ks0 = 0; ks0 < 4; ks0++) {
            const int ks = (ks0 + krot) & 3;
            uint32_t kx = ((uint32_t)ks << 5) | g2;
            uint32_t Ah[2][4];
#pragma unroll
            for (int mf = 0; mf < 2; mf++) {
                uint32_t ro = (uint32_t)((ra + mf * 16) * 128);
                ldmx4(Ah[mf], base + ro + (kx ^ Sa));
            }
#pragma unroll
            for (int mat = 0; mat < 2; mat++) {
                uint32_t bh[4];
                uint32_t bo = base + 16384u + (uint32_t)mat * 8192u + (uint32_t)(rbn * 128);
                ldmx4(bh, bo + (kx ^ Sbn));
#pragma unroll
                for (int mf = 0; mf < 2; mf++) {
#pragma unroll
                    for (int nf = 0; nf < 2; nf++)
                        mma16816(acc[mat][mf][nf], Ah[mf], bh[nf], bh[nf + 2]);
                }
            }
        }
    }

    // ---- epilogue: silu(g)*u -> h (fp16) ----
    const size_t rowbase = (z < E_NUM) ? (size_t)z * T_TOK : (size_t)E_NUM * T_TOK;
#pragma unroll
    for (int mf = 0; mf < 2; mf++) {
        int R0 = m0 + wm * 32 + mf * 16 + (lane >> 2);
#pragma unroll
        for (int nf = 0; nf < 2; nf++) {
            int C = n0 + wn * 16 + nf * 8 + (lane & 3) * 2;
            float* gf = acc[0][mf][nf];
            float* uf = acc[1][mf][nf];
#pragma unroll
            for (int hr = 0; hr < 2; hr++) {
                int R = R0 + hr * 8;
                if (R < count) {
                    float ga = gf[hr * 2], gb = gf[hr * 2 + 1];
                    float ua = uf[hr * 2], ub = uf[hr * 2 + 1];
                    float ha = ga / (1.0f + __expf(-ga)) * ua;
                    float hb = gb / (1.0f + __expf(-gb)) * ub;
                    *(__half2*)(h_buf + (rowbase + R) * (size_t)I_DIM + C) =
                        __floats2half2_rn(ha, hb);
                }
            }
        }
    }
}

// ============================================================================
// down GEMM: BM=128, BN=128, split-K=2, BK=64, 512 thr = 16 warps (4m x 4n),
// warp tile 32x32 (0.5 ldmatrix per MMA). z = expert*2 + k-half.
// Epilogue atomics make split-K free. smem/stage: A 16K | B 16K = 32KB. 2 CTAs/SM.
// ============================================================================
__global__ void __launch_bounds__(512, 2) dn_kernel(float* __restrict__ out) {
    extern __shared__ __align__(1024) char sm[];
    const int zz = blockIdx.z;
    const int kc = zz & 1;          // K half: chunks [kc*11, kc*11+11)
    const int z = zz >> 1;
    const int count = (z < E_NUM) ? g_count[z] : T_TOK;
    const int m0 = blockIdx.y * 128;
    if (m0 >= count) return;
    const int n0 = blockIdx.x * 128;

    const int tid = threadIdx.x, lane = tid & 31, wid = tid >> 5;
    const int wm = wid & 3, wn = wid >> 2;
    const uint32_t sb = smem_u32(sm);
    const size_t rowbase = (z < E_NUM) ? (size_t)z * T_TOK : (size_t)E_NUM * T_TOK;

    // ---- loader: A (h rows) + B (weight rows): 128 rows each, 4 thr/row, 2 units ----
    const int lr = tid >> 2, lj = (tid & 3) * 2;
    const char* srcA = (const char*)(h_buf + (rowbase + m0 + lr) * (size_t)I_DIM);
    const __half* wdh = (z < E_NUM) ? cdw + (size_t)z * H_DIM * I_DIM : csd;
    const char* srcB = (const char*)(wdh + (size_t)(n0 + lr) * I_DIM);
    const uint32_t SA = (uint32_t)(lr & 7) << 4;
    const uint32_t rowA = (uint32_t)(lr * 128);
    uint32_t dA[2];
#pragma unroll
    for (int uu = 0; uu < 2; uu++)
        dA[uu] = rowA + ((((uint32_t)(lj + uu)) << 4) ^ SA);

    auto load_stage = [&](int chunk, int stg) {
        uint32_t base = sb + stg * DN_STG_B;
        int koff = chunk * 128;
#pragma unroll
        for (int uu = 0; uu < 2; uu++) {
            int so = koff + (lj + uu) * 16;
            cpa(base + dA[uu],            srcA + so);
            cpa(base + 16384u + dA[uu],   srcB + so);
        }
    };

    const int ra = wm * 32 + (((lane >> 3) & 1) << 3) + (lane & 7);
    const uint32_t Sa = (uint32_t)(ra & 7) << 4;
    const int rb0 = wn * 32 + (((lane >> 3) & 1) << 3) + (lane & 7);
    const int rb1 = rb0 + 16;
    const uint32_t Sb0 = (uint32_t)(rb0 & 7) << 4;
    const uint32_t Sb1 = (uint32_t)(rb1 & 7) << 4;
    const uint32_t g2 = (uint32_t)(lane >> 4) << 4;
    const int krot = wid & 3;

    float acc[2][4][4];   // [mf][nb*2+nf][4]
#pragma unroll
    for (int a = 0; a < 2; a++)
#pragma unroll
        for (int b = 0; b < 4; b++)
#pragma unroll
            for (int c = 0; c < 4; c++) acc[a][b][c] = 0.0f;

    const int c0 = kc * 11;
    const int NCH = 11;           // chunks per K half (I_DIM/64 = 22 total)
    load_stage(c0, 0); CPA_COMMIT();
    load_stage(c0 + 1, 1); CPA_COMMIT();

    for (int cc = 0; cc < NCH; cc++) {
        CPA_WAIT1();
        __syncthreads();
        if (cc + 2 < NCH) load_stage(c0 + cc + 2, (cc + 2) % NSTG);
        CPA_COMMIT();
        uint32_t base = sb + (cc % NSTG) * DN_STG_B;
#pragma unroll
        for (int ks0 = 0; ks0 < 4; ks0++) {
            const int ks = (ks0 + krot) & 3;
            uint32_t kx = ((uint32_t)ks << 5) | g2;
            uint32_t Ah[2][4];
#pragma unroll
            for (int mf = 0; mf < 2; mf++) {
                uint32_t ro = (uint32_t)((ra + mf * 16) * 128);
                ldmx4(Ah[mf], base + ro + (kx ^ Sa));
            }
#pragma unroll
            for (int nb = 0; nb < 2; nb++) {
                uint32_t bh[4];
                uint32_t ro = (uint32_t)((nb ? rb1 : rb0) * 128);
                uint32_t Sx = nb ? Sb1 : Sb0;
                ldmx4(bh, base + 16384u + ro + (kx ^ Sx));
#pragma unroll
                for (int mf = 0; mf < 2; mf++) {
#pragma unroll
                    for (int nf = 0; nf < 2; nf++)
                        mma16816(acc[mf][nb * 2 + nf], Ah[mf], bh[nf], bh[nf + 2]);
                }
            }
        }
    }

    // ---- epilogue: weighted atomic scatter ----
#pragma unroll
    for (int mf = 0; mf < 2; mf++) {
        int R0 = m0 + wm * 32 + mf * 16 + (lane >> 2);
#pragma unroll
        for (int hr = 0; hr < 2; hr++) {
            int R = R0 + hr * 8;
            if (R < count) {
                int t; float wt;
                if (z < E_NUM) { t = g_tok[z * T_TOK + R]; wt = g_wt[z * T_TOK + R]; }
                else           { t = R; wt = 1.0f; }
                float* orow = out + (size_t)t * H_DIM;
#pragma unroll
                for (int q = 0; q < 4; q++) {
                    int C = n0 + wn * 32 + q * 8 + (lane & 3) * 2;
                    atomicAdd(&orow[C],     wt * acc[mf][q][hr * 2]);
                    atomicAdd(&orow[C + 1], wt * acc[mf][q][hr * 2 + 1]);
                }
            }
        }
    }
}

// ---------------- launch ----------------
extern "C" void kernel_launch(void* const* d_in, const int* in_sizes, int n_in,
                              void* d_out, int out_size) {
    const float* x   = (const float*)d_in[0];
    const float* gw  = (const float*)d_in[1];
    const float* egw = (const float*)d_in[2];
    const float* euw = (const float*)d_in[3];
    const float* edw = (const float*)d_in[4];
    const float* sgw = (const float*)d_in[5];
    const float* suw = (const float*)d_in[6];
    const float* sdw = (const float*)d_in[7];
    float* out = (float*)d_out;

    cudaFuncSetAttribute(gu_kernel, cudaFuncAttributeMaxDynamicSharedMemorySize, SMEM_TOT);
    cudaFuncSetAttribute(dn_kernel, cudaFuncAttributeMaxDynamicSharedMemorySize, DN_SMEM_TOT);

    // 1: zero out + reset counts + cvt(x, shared gate, shared up)
    zero_cvt_kernel<<<1480, 256>>>(out, x, sgw, suw);
    // 2: routing (blocks 0..127) + gate/up weight conversion (blocks 128..)
    routing_cvt_kernel<<<128 + 2960, 256>>>(x, gw, egw, euw);
    // 3: gate+up GEMM (z 0..8) + hidden down-weight conversion (z == 9)
    gu_kernel<<<dim3(I_DIM / 64, T_TOK / 128, E_NUM + 2), 512, SMEM_TOT>>>(edw, sdw);
    // 4: down GEMM: BN=128, split-K=2 (z = expert*2 + half)
    dn_kernel<<<dim3(H_DIM / 128, T_TOK / 128, (E_NUM + 1) * 2), 512, DN_SMEM_TOT>>>(out);
}